// round 3
// baseline (speedup 1.0000x reference)
#include <cuda_runtime.h>
#include <cstdint>

#define HDIM 128
#define MAXN 65536

// Scratch (allocation-free rule: static __device__ arrays)
__device__ __align__(16) float g_buf0[(size_t)MAXN * HDIM]; // hs / next-layer input
__device__ __align__(16) float g_buf1[(size_t)MAXN * HDIM]; // accumulator
__device__ float g_dis[MAXN];
__device__ int   g_deg[MAXN];
__device__ int   g_is64;   // 1 if edge_index is int64, 0 if int32

// ---------------- dtype probe ----------------
// Reads the first min(64,E) *src* entries as int64. Safe for both dtypes:
// indices < E stay inside the buffer whether it holds 2E int32 or 2E int64.
__global__ void k_detect(const void* __restrict__ ei, int E, int N) {
    if (threadIdx.x != 0 || blockIdx.x != 0) return;
    const long long* p = (const long long*)ei;
    int is64 = 1;
    int n = E < 64 ? E : 64;
    for (int i = 0; i < n; i++) {
        long long v = p[i];
        if (v < 0 || v >= (long long)N) { is64 = 0; break; }
    }
    g_is64 = is64;
}

__device__ __forceinline__ int load_idx(const void* __restrict__ ei, size_t pos) {
    return g_is64 ? (int)((const long long*)ei)[pos]
                  : ((const int*)ei)[pos];
}

// ---------------- degree / normalization ----------------
__global__ void k_deg_init(int N) {
    int i = blockIdx.x * blockDim.x + threadIdx.x;
    if (i < N) g_deg[i] = 1;  // self loop
}

__global__ void k_deg_count(const void* __restrict__ ei, int E, int N) {
    int e = blockIdx.x * blockDim.x + threadIdx.x;
    if (e >= E) return;
    int d = load_idx(ei, (size_t)E + e);
    if ((unsigned)d < (unsigned)N) atomicAdd(&g_deg[d], 1);
}

__global__ void k_dis(int N) {
    int i = blockIdx.x * blockDim.x + threadIdx.x;
    if (i < N) g_dis[i] = rsqrtf((float)g_deg[i]);
}

// ---------------- GEMM: hs = (X @ W) * dis[row], written to buf0 AND buf1 ----
// block = 256 threads, tile = 64 rows x 128 cols; thread computes 8 rows x 4 cols.
// X == nullptr means "read layer input from g_buf0" (safe: block reads its own
// rows fully into smem before writing them back).
__global__ __launch_bounds__(256) void k_gemm_scale(
    const float* __restrict__ X, const float* __restrict__ W, int N)
{
    __shared__ float sA[64][HDIM];
    const float* Xp = X ? X : g_buf0;

    int tx = threadIdx.x & 31;   // column group (4 cols)
    int ty = threadIdx.x >> 5;   // warp id -> 8 rows
    int rowBase = blockIdx.x * 64;

    // Load A tile (coalesced float4). Rows beyond N -> zeros.
    for (int t = threadIdx.x; t < 64 * (HDIM / 4); t += 256) {
        int r  = t >> 5;         // 32 float4 per row
        int c4 = t & 31;
        int row = rowBase + r;
        float4 v = make_float4(0.f, 0.f, 0.f, 0.f);
        if (row < N) v = *(const float4*)(Xp + (size_t)row * HDIM + c4 * 4);
        *(float4*)(&sA[r][c4 * 4]) = v;
    }
    __syncthreads();

    float acc[8][4];
    #pragma unroll
    for (int i = 0; i < 8; i++)
        #pragma unroll
        for (int c = 0; c < 4; c++) acc[i][c] = 0.f;

    #pragma unroll 4
    for (int k = 0; k < HDIM; k++) {
        float4 w = __ldg((const float4*)(W + (size_t)k * HDIM + tx * 4));
        #pragma unroll
        for (int i = 0; i < 8; i++) {
            float a = sA[ty * 8 + i][k];   // warp-broadcast from smem
            acc[i][0] = fmaf(a, w.x, acc[i][0]);
            acc[i][1] = fmaf(a, w.y, acc[i][1]);
            acc[i][2] = fmaf(a, w.z, acc[i][2]);
            acc[i][3] = fmaf(a, w.w, acc[i][3]);
        }
    }

    #pragma unroll
    for (int i = 0; i < 8; i++) {
        int row = rowBase + ty * 8 + i;
        if (row < N) {
            float s = g_dis[row];
            float4 v = make_float4(acc[i][0] * s, acc[i][1] * s,
                                   acc[i][2] * s, acc[i][3] * s);
            size_t off = (size_t)row * HDIM + tx * 4;
            *(float4*)(g_buf0 + off) = v;   // hs for gathering
            *(float4*)(g_buf1 + off) = v;   // acc init (= self-loop term)
        }
    }
}

// ---------------- edge scatter: acc[dst] += hs[src] ----------------
// One warp per edge; each lane handles one float4; vectorized L2 red.
__global__ __launch_bounds__(256) void k_scatter(const void* __restrict__ ei,
                                                 int E, int N)
{
    int e = blockIdx.x * 8 + (threadIdx.x >> 5);
    if (e >= E) return;
    int lane = threadIdx.x & 31;
    int s = load_idx(ei, e);
    int d = load_idx(ei, (size_t)E + e);
    if ((unsigned)s >= (unsigned)N || (unsigned)d >= (unsigned)N) return;
    float4 v = __ldg((const float4*)(g_buf0 + (size_t)s * HDIM + lane * 4));
    float* p = g_buf1 + (size_t)d * HDIM + lane * 4;
    asm volatile("red.global.add.v4.f32 [%0], {%1,%2,%3,%4};"
                 :: "l"(p), "f"(v.x), "f"(v.y), "f"(v.z), "f"(v.w)
                 : "memory");
}

// ---------------- finalize: out = relu(dis[i]*acc + b) ----------------
__global__ void k_finalize(const float* __restrict__ b, float* __restrict__ out,
                           int N, int toBuf0)
{
    int idx = blockIdx.x * blockDim.x + threadIdx.x;  // over N*32 float4s
    if (idx >= N * 32) return;
    int i  = idx >> 5;
    int c4 = idx & 31;
    float s = g_dis[i];
    float4 a  = *(const float4*)(g_buf1 + (size_t)idx * 4);
    float4 bb = __ldg((const float4*)(b + c4 * 4));
    float4 r;
    r.x = fmaxf(fmaf(s, a.x, bb.x), 0.f);
    r.y = fmaxf(fmaf(s, a.y, bb.y), 0.f);
    r.z = fmaxf(fmaf(s, a.z, bb.z), 0.f);
    r.w = fmaxf(fmaf(s, a.w, bb.w), 0.f);
    if (toBuf0) *(float4*)(g_buf0 + (size_t)idx * 4) = r;
    else        ((float4*)out)[idx] = r;
}

extern "C" void kernel_launch(void* const* d_in, const int* in_sizes, int n_in,
                              void* d_out, int out_size)
{
    const float* x  = (const float*)d_in[0];
    const void*  ei = d_in[1];
    const float* W1 = (const float*)d_in[2];
    const float* b1 = (const float*)d_in[3];
    const float* W2 = (const float*)d_in[4];
    const float* b2 = (const float*)d_in[5];

    int H = in_sizes[3];            // 128
    int D = in_sizes[2] / H;        // 128
    int N = in_sizes[0] / D;        // 50000
    int E = in_sizes[1] / 2;        // 1600000
    (void)D; (void)n_in; (void)out_size;

    // dtype probe + normalization
    k_detect<<<1, 32>>>(ei, E, N);
    k_deg_init<<<(N + 255) / 256, 256>>>(N);
    k_deg_count<<<(E + 255) / 256, 256>>>(ei, E, N);
    k_dis<<<(N + 255) / 256, 256>>>(N);

    int gemmBlocks = (N + 63) / 64;
    int scatBlocks = (E + 7) / 8;
    int finBlocks  = (N * 32 + 255) / 256;

    // layer 1
    k_gemm_scale<<<gemmBlocks, 256>>>(x, W1, N);
    k_scatter<<<scatBlocks, 256>>>(ei, E, N);
    k_finalize<<<finBlocks, 256>>>(b1, nullptr, N, 1);

    // layer 2
    k_gemm_scale<<<gemmBlocks, 256>>>(nullptr, W2, N);
    k_scatter<<<scatBlocks, 256>>>(ei, E, N);
    k_finalize<<<finBlocks, 256>>>(b2, (float*)d_out, N, 0);
}